// round 16
// baseline (speedup 1.0000x reference)
#include <cuda_runtime.h>
#include <math.h>
#include <float.h>

#define NCH 85
#define NTC 6
#define SS  (52 * 52)
#define LOG2E 1.44269504088896340736f

// g_acc: [0]=sum_noobj [1]=cnt_noobj [2]=sum_obj [3]=cnt_obj
//        [4]=sum_ciou [5]=sum_box [6]=sum_cls
// zero at load; last block resets -> replay-safe.
__device__ double g_acc[7];
__device__ unsigned int g_done;

__device__ __forceinline__ float warp_sum(float v) {
#pragma unroll
    for (int o = 16; o; o >>= 1) v += __shfl_xor_sync(0xffffffffu, v, o);
    return v;
}

// FFMA-pipe exp2: magic-number round + degree-5 poly (|x| small here).
__device__ __forceinline__ float fast_exp2(float x) {
    float r  = x + 12582912.0f;                 // 1.5 * 2^23
    int   ik = __float_as_int(r) - 0x4B400000;
    float f  = x - (r - 12582912.0f);           // f in [-0.5, 0.5]
    float p  = 1.3333558e-3f;
    p = fmaf(p, f, 9.6181291e-3f);
    p = fmaf(p, f, 5.5504109e-2f);
    p = fmaf(p, f, 2.4022651e-1f);
    p = fmaf(p, f, 6.9314718e-1f);
    p = fmaf(p, f, 1.0f);
    return p * __int_as_float((ik + 127) << 23);
}

// FFMA-pipe natural log for x > 0 (cephes-style, ~1e-7 rel).
__device__ __forceinline__ float fast_ln(float x) {
    const int bits = __float_as_int(x);
    const int e    = (bits - 0x3f3504f3) >> 23;            // sqrt(0.5) centering
    const float m  = __int_as_float(bits - (e << 23));     // [0.7071, 1.4142)
    const float f  = m - 1.0f;
    const float z  = f * f;
    float p = 7.0376836292e-2f;
    p = fmaf(p, f, -1.1514610310e-1f);
    p = fmaf(p, f,  1.1676998740e-1f);
    p = fmaf(p, f, -1.2420140846e-1f);
    p = fmaf(p, f,  1.4249322787e-1f);
    p = fmaf(p, f, -1.6668057665e-1f);
    p = fmaf(p, f,  2.0000714765e-1f);
    p = fmaf(p, f, -2.4999993993e-1f);
    p = fmaf(p, f,  3.3333331174e-1f);
    const float r = fmaf(f * z, p, fmaf(-0.5f, z, f));
    return fmaf((float)e, 0.69314718055994531f, r);
}

// atan(x) for x > 0: range-reduce to [0,1], 6-term minimax (abs err ~2e-7).
__device__ __forceinline__ float fatan_pos(float x) {
    const bool big = (x > 1.0f);
    const float t = big ? __fdividef(1.0f, x) : x;
    const float s = t * t;
    float p = -1.1721200e-2f;
    p = fmaf(p, s,  5.2653322e-2f);
    p = fmaf(p, s, -1.1643287e-1f);
    p = fmaf(p, s,  1.9354346e-1f);
    p = fmaf(p, s, -3.3262347e-1f);
    p = fmaf(p, s,  9.9997726e-1f);
    const float r = t * p;
    return big ? (1.57079632679f - r) : r;
}

__device__ __forceinline__ float sigmoidf_(float x) {
    return 1.0f / (1.0f + __expf(-x));
}

// ── single fused pass: stream + obj scalars + in-warp softmax + finalize ──
__global__ __launch_bounds__(256)
void yolo_kernel(const float* __restrict__ pred,
                 const float* __restrict__ tgt,
                 const float* __restrict__ anc,
                 int ncells, float* __restrict__ out) {
    const int lane = threadIdx.x & 31;
    const int wib  = threadIdx.x >> 5;
    const int c    = blockIdx.x * 256 + threadIdx.x;
    const bool valid = (c < ncells);

    const float a0w = __ldg(anc + 0), a0h = __ldg(anc + 1);
    const float a1w = __ldg(anc + 2), a1h = __ldg(anc + 3);
    const float a2w = __ldg(anc + 4), a2h = __ldg(anc + 5);

    const float t0 = valid ? __ldg(tgt + (size_t)c * NTC) : -1.0f;
    const float p0 = valid ? __ldg(pred + (size_t)c * NCH) : 0.0f;

    float s_noobj = 0.f, c_noobj = 0.f;
    float s_obj = 0.f, c_obj = 0.f, s_ciou = 0.f, s_box = 0.f;
    float t5 = 0.f;

    if (t0 == 0.0f) {
        s_noobj = fmaxf(p0, 0.0f) + __logf(1.0f + __expf(-fabsf(p0)));
        c_noobj = 1.0f;
    }

    if (t0 == 1.0f) {
        c_obj = 1.0f;
        const float* p = pred + (size_t)c * NCH;
        const float* t = tgt  + (size_t)c * NTC;
        const float p1 = __ldg(p + 1);
        const float p2 = __ldg(p + 2);
        const float p3 = __ldg(p + 3);
        const float p4 = __ldg(p + 4);
        const float2 t01 = __ldg((const float2*)(t + 0));
        const float2 t23 = __ldg((const float2*)(t + 2));
        const float2 t45 = __ldg((const float2*)(t + 4));
        const float t1 = t01.y, t2 = t23.x, t3 = t23.y, t4 = t45.x;
        t5 = t45.y;

        const int a = (c / SS) % 3;
        const float aw = (a == 0) ? a0w : ((a == 1) ? a1w : a2w);
        const float ah = (a == 0) ? a0h : ((a == 1) ? a1h : a2h);

        const float sx = sigmoidf_(p1);
        const float sy = sigmoidf_(p2);
        const float bw = __expf(p3) * aw;
        const float bh = __expf(p4) * ah;

        const float b1x1 = sx - 0.5f * bw, b1x2 = sx + 0.5f * bw;
        const float b1y1 = sy - 0.5f * bh, b1y2 = sy + 0.5f * bh;
        const float b2x1 = t1 - 0.5f * t3, b2x2 = t1 + 0.5f * t3;
        const float b2y1 = t2 - 0.5f * t4, b2y2 = t2 + 0.5f * t4;
        const float iw = fmaxf(fminf(b1x2, b2x2) - fmaxf(b1x1, b2x1), 0.0f);
        const float ih = fmaxf(fminf(b1y2, b2y2) - fmaxf(b1y1, b2y1), 0.0f);
        const float inter = iw * ih;
        const float area1 = fabsf(bw * bh);
        const float area2 = fabsf(t3 * t4);
        const float iou_m = inter / (area1 + area2 - inter + 1e-6f);

        s_obj = fmaxf(p0, 0.0f) - p0 * iou_m + __logf(1.0f + __expf(-fabsf(p0)));

        const float uni  = bw * bh + t3 * t4 - inter;
        const float iou  = inter / (uni + 1e-7f);
        const float cw   = fmaxf(b1x2, b2x2) - fminf(b1x1, b2x1);
        const float chh  = fmaxf(b1y2, b2y2) - fminf(b1y1, b2y1);
        const float diag = cw * cw + chh * chh + 1e-7f;
        const float dx   = sx - t1;
        const float dy   = sy - t2;
        const float diou = 1.0f - iou + (dx * dx + dy * dy) / diag;
        const float dat  = fatan_pos(t3 / (t4 + 1e-7f)) - fatan_pos(bw / (bh + 1e-7f));
        const float vv   = 0.40528473456f * dat * dat;   // 4/pi^2
        const float alpha = vv / (1.0f - iou + vv + 1e-7f);
        s_ciou = diou + alpha * vv;

        const float lw = __logf(1e-16f + t3 / aw);
        const float lh = __logf(1e-16f + t4 / ah);
        const float d1 = sx - t1, d2 = sy - t2, d3 = p3 - lw, d4 = p4 - lh;
        s_box = d1 * d1 + d2 * d2 + d3 * d3 + d4 * d4;
    }

    // ---- in-warp softmax over this warp's obj cells ----
    float s_ln = 0.f;   // warp-uniform: sum of ln(Z)
    float s_x  = 0.f;   // per-lane: -label logits (owner-lane accumulation)
    unsigned m = __ballot_sync(0xffffffffu, t0 == 1.0f);
    while (m) {
        const int l = __ffs(m) - 1;
        m &= m - 1;
        const int   cl  = __shfl_sync(0xffffffffu, c,  l);
        const float t5l = __shfl_sync(0xffffffffu, t5, l);

        const float* pc = pred + (size_t)cl * NCH;
        const float v0 = __ldg(pc + lane);
        const float v1 = __ldg(pc + 32 + lane);
        const float v2 = (lane < 21) ? __ldg(pc + 64 + lane) : 0.0f;

        float e = fast_exp2(v1 * LOG2E);
        if (lane >= 5) e += fast_exp2(v0 * LOG2E);
        if (lane < 21) e += fast_exp2(v2 * LOG2E);
        const float Z = warp_sum(e);

        s_ln += fast_ln(Z);

        const int lch = 5 + (int)t5l;
        if (lane == (lch & 31))
            s_x -= (lch < 32) ? v0 : ((lch < 64) ? v1 : v2);
    }

    // ---- reductions ----
    s_noobj = warp_sum(s_noobj);
    c_noobj = warp_sum(c_noobj);
    s_obj   = warp_sum(s_obj);
    c_obj   = warp_sum(c_obj);
    s_ciou  = warp_sum(s_ciou);
    s_box   = warp_sum(s_box);
    s_x     = warp_sum(s_x);
    const float s_cls = s_ln + s_x;   // valid on lane 0 (s_ln uniform)

    __shared__ float sm[7][8];
    if (lane == 0) {
        sm[0][wib] = s_noobj; sm[1][wib] = c_noobj;
        sm[2][wib] = s_obj;   sm[3][wib] = c_obj;
        sm[4][wib] = s_ciou;  sm[5][wib] = s_box;
        sm[6][wib] = s_cls;
    }
    __syncthreads();
    if (threadIdx.x < 7) {
        float s = 0.f;
#pragma unroll
        for (int w = 0; w < 8; w++) s += sm[threadIdx.x][w];
        atomicAdd(&g_acc[threadIdx.x], (double)s);
    }
    __threadfence();

    // last-block finalize + state reset
    __shared__ int is_last;
    if (threadIdx.x == 0) {
        unsigned prev = atomicAdd(&g_done, 1u);
        is_last = (prev == gridDim.x - 1u) ? 1 : 0;
    }
    __syncthreads();
    if (is_last && threadIdx.x == 0) {
        const double cobj   = fmax(g_acc[3], 1.0);
        const double cnoobj = fmax(g_acc[1], 1.0);
        const double noobj  = g_acc[0] / cnoobj;
        const double objl   = g_acc[2] / cobj;
        const double cioul  = g_acc[4] / cobj;
        const double boxl   = (g_acc[5] / cobj) * 0.25;
        const double clsl   = g_acc[6] / cobj;
        out[0] = (float)(10.0 * boxl + 10.0 * objl + noobj + clsl + cioul);
#pragma unroll
        for (int k = 0; k < 7; k++) g_acc[k] = 0.0;
        __threadfence();
        g_done = 0;
    }
}

extern "C" void kernel_launch(void* const* d_in, const int* in_sizes, int n_in,
                              void* d_out, int out_size) {
    int ip = 0, it = 1, ia = 2;
    long best = -1;
    for (int i = 0; i < n_in; i++) {
        if (in_sizes[i] == 6) ia = i;
        if ((long)in_sizes[i] > best) { best = in_sizes[i]; ip = i; }
    }
    for (int i = 0; i < n_in; i++) if (i != ip && i != ia) it = i;

    const float* pred = (const float*)d_in[ip];
    const float* tgt  = (const float*)d_in[it];
    const float* anc  = (const float*)d_in[ia];
    const int ncells  = in_sizes[ip] / NCH;

    const int nblk = (ncells + 255) / 256;
    yolo_kernel<<<nblk, 256>>>(pred, tgt, anc, ncells, (float*)d_out);
}

// round 17
// speedup vs baseline: 1.0296x; 1.0296x over previous
#include <cuda_runtime.h>
#include <math.h>
#include <float.h>

#define NCH 85
#define NTC 6
#define SS  (52 * 52)
#define LOG2E 1.44269504088896340736f
#define TPB 512
#define WPB 16

// g_acc: [0]=sum_noobj [1]=cnt_noobj [2]=sum_obj [3]=cnt_obj
//        [4]=sum_ciou [5]=sum_box [6]=sum_cls
// zero at load; last block resets -> replay-safe.
__device__ double g_acc[7];
__device__ unsigned int g_done;

__device__ __forceinline__ float warp_sum(float v) {
#pragma unroll
    for (int o = 16; o; o >>= 1) v += __shfl_xor_sync(0xffffffffu, v, o);
    return v;
}

// FFMA-pipe exp2: magic-number round + degree-5 poly (|x| small here).
__device__ __forceinline__ float fast_exp2(float x) {
    float r  = x + 12582912.0f;                 // 1.5 * 2^23
    int   ik = __float_as_int(r) - 0x4B400000;
    float f  = x - (r - 12582912.0f);           // f in [-0.5, 0.5]
    float p  = 1.3333558e-3f;
    p = fmaf(p, f, 9.6181291e-3f);
    p = fmaf(p, f, 5.5504109e-2f);
    p = fmaf(p, f, 2.4022651e-1f);
    p = fmaf(p, f, 6.9314718e-1f);
    p = fmaf(p, f, 1.0f);
    return p * __int_as_float((ik + 127) << 23);
}

// FFMA-pipe natural log for x > 0 (cephes-style, ~1e-7 rel).
__device__ __forceinline__ float fast_ln(float x) {
    const int bits = __float_as_int(x);
    const int e    = (bits - 0x3f3504f3) >> 23;            // sqrt(0.5) centering
    const float m  = __int_as_float(bits - (e << 23));     // [0.7071, 1.4142)
    const float f  = m - 1.0f;
    const float z  = f * f;
    float p = 7.0376836292e-2f;
    p = fmaf(p, f, -1.1514610310e-1f);
    p = fmaf(p, f,  1.1676998740e-1f);
    p = fmaf(p, f, -1.2420140846e-1f);
    p = fmaf(p, f,  1.4249322787e-1f);
    p = fmaf(p, f, -1.6668057665e-1f);
    p = fmaf(p, f,  2.0000714765e-1f);
    p = fmaf(p, f, -2.4999993993e-1f);
    p = fmaf(p, f,  3.3333331174e-1f);
    const float r = fmaf(f * z, p, fmaf(-0.5f, z, f));
    return fmaf((float)e, 0.69314718055994531f, r);
}

// atan(x) for x > 0: range-reduce to [0,1], 6-term minimax (abs err ~2e-7).
__device__ __forceinline__ float fatan_pos(float x) {
    const bool big = (x > 1.0f);
    const float t = big ? __fdividef(1.0f, x) : x;
    const float s = t * t;
    float p = -1.1721200e-2f;
    p = fmaf(p, s,  5.2653322e-2f);
    p = fmaf(p, s, -1.1643287e-1f);
    p = fmaf(p, s,  1.9354346e-1f);
    p = fmaf(p, s, -3.3262347e-1f);
    p = fmaf(p, s,  9.9997726e-1f);
    const float r = t * p;
    return big ? (1.57079632679f - r) : r;
}

__device__ __forceinline__ float sigmoidf_(float x) {
    return 1.0f / (1.0f + __expf(-x));
}

// ── single fused pass, pair-pipelined softmax ─────────────────────────────
__global__ __launch_bounds__(TPB)
void yolo_kernel(const float* __restrict__ pred,
                 const float* __restrict__ tgt,
                 const float* __restrict__ anc,
                 int ncells, float* __restrict__ out) {
    const int lane = threadIdx.x & 31;
    const int wib  = threadIdx.x >> 5;
    const int c    = blockIdx.x * TPB + threadIdx.x;
    const bool valid = (c < ncells);

    const float a0w = __ldg(anc + 0), a0h = __ldg(anc + 1);
    const float a1w = __ldg(anc + 2), a1h = __ldg(anc + 3);
    const float a2w = __ldg(anc + 4), a2h = __ldg(anc + 5);

    const float t0 = valid ? __ldg(tgt + (size_t)c * NTC) : -1.0f;
    const float p0 = valid ? __ldg(pred + (size_t)c * NCH) : 0.0f;

    float s_noobj = 0.f, c_noobj = 0.f;
    float s_obj = 0.f, c_obj = 0.f, s_ciou = 0.f, s_box = 0.f;
    float t5 = 0.f;

    if (t0 == 0.0f) {
        s_noobj = fmaxf(p0, 0.0f) + __logf(1.0f + __expf(-fabsf(p0)));
        c_noobj = 1.0f;
    }

    if (t0 == 1.0f) {
        c_obj = 1.0f;
        const float* p = pred + (size_t)c * NCH;
        const float* t = tgt  + (size_t)c * NTC;
        const float p1 = __ldg(p + 1);
        const float p2 = __ldg(p + 2);
        const float p3 = __ldg(p + 3);
        const float p4 = __ldg(p + 4);
        const float2 t01 = __ldg((const float2*)(t + 0));
        const float2 t23 = __ldg((const float2*)(t + 2));
        const float2 t45 = __ldg((const float2*)(t + 4));
        const float t1 = t01.y, t2 = t23.x, t3 = t23.y, t4 = t45.x;
        t5 = t45.y;

        const int a = (c / SS) % 3;
        const float aw = (a == 0) ? a0w : ((a == 1) ? a1w : a2w);
        const float ah = (a == 0) ? a0h : ((a == 1) ? a1h : a2h);

        const float sx = sigmoidf_(p1);
        const float sy = sigmoidf_(p2);
        const float bw = __expf(p3) * aw;
        const float bh = __expf(p4) * ah;

        const float b1x1 = sx - 0.5f * bw, b1x2 = sx + 0.5f * bw;
        const float b1y1 = sy - 0.5f * bh, b1y2 = sy + 0.5f * bh;
        const float b2x1 = t1 - 0.5f * t3, b2x2 = t1 + 0.5f * t3;
        const float b2y1 = t2 - 0.5f * t4, b2y2 = t2 + 0.5f * t4;
        const float iw = fmaxf(fminf(b1x2, b2x2) - fmaxf(b1x1, b2x1), 0.0f);
        const float ih = fmaxf(fminf(b1y2, b2y2) - fmaxf(b1y1, b2y1), 0.0f);
        const float inter = iw * ih;
        const float area1 = fabsf(bw * bh);
        const float area2 = fabsf(t3 * t4);
        const float iou_m = inter / (area1 + area2 - inter + 1e-6f);

        s_obj = fmaxf(p0, 0.0f) - p0 * iou_m + __logf(1.0f + __expf(-fabsf(p0)));

        const float uni  = bw * bh + t3 * t4 - inter;
        const float iou  = inter / (uni + 1e-7f);
        const float cw   = fmaxf(b1x2, b2x2) - fminf(b1x1, b2x1);
        const float chh  = fmaxf(b1y2, b2y2) - fminf(b1y1, b2y1);
        const float diag = cw * cw + chh * chh + 1e-7f;
        const float dx   = sx - t1;
        const float dy   = sy - t2;
        const float diou = 1.0f - iou + (dx * dx + dy * dy) / diag;
        const float dat  = fatan_pos(t3 / (t4 + 1e-7f)) - fatan_pos(bw / (bh + 1e-7f));
        const float vv   = 0.40528473456f * dat * dat;   // 4/pi^2
        const float alpha = vv / (1.0f - iou + vv + 1e-7f);
        s_ciou = diou + alpha * vv;

        const float lw = __logf(1e-16f + t3 / aw);
        const float lh = __logf(1e-16f + t4 / ah);
        const float d1 = sx - t1, d2 = sy - t2, d3 = p3 - lw, d4 = p4 - lh;
        s_box = d1 * d1 + d2 * d2 + d3 * d3 + d4 * d4;
    }

    // ---- in-warp softmax, two obj cells per iteration ----
    float s_ln = 0.f;   // warp-uniform: sum of ln(Z)
    float s_x  = 0.f;   // per-lane: -label logits (owner-lane accumulation)
    unsigned m = __ballot_sync(0xffffffffu, t0 == 1.0f);
    while (m) {
        const int lA = __ffs(m) - 1;
        m &= m - 1;
        const bool two = (m != 0);
        const int lB = two ? (__ffs(m) - 1) : lA;
        if (two) m &= m - 1;

        const int   cA  = __shfl_sync(0xffffffffu, c,  lA);
        const int   cB  = __shfl_sync(0xffffffffu, c,  lB);
        const float tA  = __shfl_sync(0xffffffffu, t5, lA);
        const float tB  = __shfl_sync(0xffffffffu, t5, lB);

        const float* pa = pred + (size_t)cA * NCH;
        const float* pb = pred + (size_t)cB * NCH;
        // all six loads issue together -> MLP 6
        const float a0 = __ldg(pa + lane);
        const float a1 = __ldg(pa + 32 + lane);
        const float a2 = (lane < 21) ? __ldg(pa + 64 + lane) : 0.0f;
        const float b0 = __ldg(pb + lane);
        const float b1 = __ldg(pb + 32 + lane);
        const float b2 = (lane < 21) ? __ldg(pb + 64 + lane) : 0.0f;

        float eA = fast_exp2(a1 * LOG2E);
        float eB = fast_exp2(b1 * LOG2E);
        if (lane >= 5) { eA += fast_exp2(a0 * LOG2E); eB += fast_exp2(b0 * LOG2E); }
        if (lane < 21) { eA += fast_exp2(a2 * LOG2E); eB += fast_exp2(b2 * LOG2E); }

        // two interleaved reduction trees
        float vA = eA, vB = eB;
#pragma unroll
        for (int o = 16; o; o >>= 1) {
            vA += __shfl_xor_sync(0xffffffffu, vA, o);
            vB += __shfl_xor_sync(0xffffffffu, vB, o);
        }

        s_ln += fast_ln(vA);
        if (two) s_ln += fast_ln(vB);

        const int chA = 5 + (int)tA;
        const int chB = 5 + (int)tB;
        if (lane == (chA & 31))
            s_x -= (chA < 32) ? a0 : ((chA < 64) ? a1 : a2);
        if (two && lane == (chB & 31))
            s_x -= (chB < 32) ? b0 : ((chB < 64) ? b1 : b2);
    }

    // ---- reductions ----
    s_noobj = warp_sum(s_noobj);
    c_noobj = warp_sum(c_noobj);
    s_obj   = warp_sum(s_obj);
    c_obj   = warp_sum(c_obj);
    s_ciou  = warp_sum(s_ciou);
    s_box   = warp_sum(s_box);
    s_x     = warp_sum(s_x);
    const float s_cls = s_ln + s_x;   // valid on lane 0 (s_ln uniform)

    __shared__ float sm[7][WPB];
    if (lane == 0) {
        sm[0][wib] = s_noobj; sm[1][wib] = c_noobj;
        sm[2][wib] = s_obj;   sm[3][wib] = c_obj;
        sm[4][wib] = s_ciou;  sm[5][wib] = s_box;
        sm[6][wib] = s_cls;
    }
    __syncthreads();
    if (threadIdx.x < 7) {
        float s = 0.f;
#pragma unroll
        for (int w = 0; w < WPB; w++) s += sm[threadIdx.x][w];
        atomicAdd(&g_acc[threadIdx.x], (double)s);
    }
    __threadfence();

    // last-block finalize + state reset
    __shared__ int is_last;
    if (threadIdx.x == 0) {
        unsigned prev = atomicAdd(&g_done, 1u);
        is_last = (prev == gridDim.x - 1u) ? 1 : 0;
    }
    __syncthreads();
    if (is_last && threadIdx.x == 0) {
        const double cobj   = fmax(g_acc[3], 1.0);
        const double cnoobj = fmax(g_acc[1], 1.0);
        const double noobj  = g_acc[0] / cnoobj;
        const double objl   = g_acc[2] / cobj;
        const double cioul  = g_acc[4] / cobj;
        const double boxl   = (g_acc[5] / cobj) * 0.25;
        const double clsl   = g_acc[6] / cobj;
        out[0] = (float)(10.0 * boxl + 10.0 * objl + noobj + clsl + cioul);
#pragma unroll
        for (int k = 0; k < 7; k++) g_acc[k] = 0.0;
        __threadfence();
        g_done = 0;
    }
}

extern "C" void kernel_launch(void* const* d_in, const int* in_sizes, int n_in,
                              void* d_out, int out_size) {
    int ip = 0, it = 1, ia = 2;
    long best = -1;
    for (int i = 0; i < n_in; i++) {
        if (in_sizes[i] == 6) ia = i;
        if ((long)in_sizes[i] > best) { best = in_sizes[i]; ip = i; }
    }
    for (int i = 0; i < n_in; i++) if (i != ip && i != ia) it = i;

    const float* pred = (const float*)d_in[ip];
    const float* tgt  = (const float*)d_in[it];
    const float* anc  = (const float*)d_in[ia];
    const int ncells  = in_sizes[ip] / NCH;

    const int nblk = (ncells + TPB - 1) / TPB;
    yolo_kernel<<<nblk, TPB>>>(pred, tgt, anc, ncells, (float*)d_out);
}